// round 1
// baseline (speedup 1.0000x reference)
#include <cuda_runtime.h>

// Problem constants
#define NSAMP 128          // batch
#define HID   64           // hidden dim
#define NCFG  32           // LX*LY
#define NVEC  16384        // 2 * LX * D^5
#define NB    8192         // LX * D^5   (size of bot half)

// Scratch for NN correction: corr[n][k] = b2[k] + sum_j h[n][j]*W2[j][k]
__device__ float g_corr[NSAMP * NVEC];   // 8 MB

// ---------------------------------------------------------------------------
// Kernel A: the 128x64 @ 64x16384 GEMM (+bias), H computed in-block.
// grid = 128 blocks, block = 256 threads.
// Block b covers output columns [b*128, b*128+128). Thread handles one column
// for 64 of the 128 samples (tid>>7 selects which half).
// ---------------------------------------------------------------------------
__global__ void __launch_bounds__(256) nn_gemm_kernel(
    const int*   __restrict__ cfg,
    const float* __restrict__ W1,
    const float* __restrict__ b1,
    const float* __restrict__ W2,
    const float* __restrict__ b2)
{
    __shared__ float sh_h[NSAMP * HID];   // 32 KB
    const int tid = threadIdx.x;

    // H = relu(cfg @ W1 + b1), computed redundantly per block (256K MACs, trivial)
    for (int m = tid; m < NSAMP * HID; m += 256) {
        const int n = m >> 6;
        const int o = m & 63;
        float acc = b1[o];
        const int* crow = cfg + n * NCFG;
        #pragma unroll
        for (int i = 0; i < NCFG; i++)
            acc = fmaf((float)crow[i], W1[i * HID + o], acc);
        sh_h[m] = fmaxf(acc, 0.0f);
    }
    __syncthreads();

    const int k     = blockIdx.x * 128 + (tid & 127);
    const int nbase = (tid >> 7) * 64;

    // W2 column in registers (64 regs), coalesced loads (warp spans consecutive k)
    float w[HID];
    #pragma unroll
    for (int j = 0; j < HID; j++) w[j] = W2[j * NVEC + k];
    const float bk = b2[k];

    #pragma unroll
    for (int c = 0; c < 4; c++) {
        const int n0 = nbase + c * 16;
        float acc[16];
        #pragma unroll
        for (int t = 0; t < 16; t++) acc[t] = bk;
        #pragma unroll
        for (int t = 0; t < 16; t++) {
            const float4* h4 = (const float4*)(sh_h + (n0 + t) * HID);
            #pragma unroll
            for (int j4 = 0; j4 < 16; j4++) {
                const float4 hv = h4[j4];   // warp-uniform -> smem broadcast
                acc[t] = fmaf(hv.x, w[4 * j4 + 0], acc[t]);
                acc[t] = fmaf(hv.y, w[4 * j4 + 1], acc[t]);
                acc[t] = fmaf(hv.z, w[4 * j4 + 2], acc[t]);
                acc[t] = fmaf(hv.w, w[4 * j4 + 3], acc[t]);
            }
        }
        #pragma unroll
        for (int t = 0; t < 16; t++)
            g_corr[(n0 + t) * NVEC + k] = acc[t];   // coalesced
    }
}

// ---------------------------------------------------------------------------
// Kernel B: per-sample tensor contraction + factored transfer-matrix scan.
// grid = 128 (one block per sample), block = 256 threads, ~45 KB static smem.
//
// s[x][y][a][b][c][d] = A[x,y,a,b,c,d, cfg[x,y]]
// bot2[x,i=(l,L), j=(r,R), U] = sum_u s(x,0)[l,r,0,u] * s(x,1)[L,R,u,U] + eta*corr
// top2[x,i=(l,L), j=(r,R), d] = sum_u s(x,2)[l,r,d,u] * s(x,3)[L,R,u,0] + eta*corr
// v'[(j,J)] = sum_{i,I,U} v[(i,I)] * bot2[i,j,U] * top2[I,J,U]   (8 steps)
// out[n] = v[0]
// ---------------------------------------------------------------------------
__global__ void __launch_bounds__(256) contract_kernel(
    const int*   __restrict__ cfg,
    const float* __restrict__ A,
    float*       __restrict__ out)
{
    __shared__ float sh_s[32 * 256];   // 32 KB: 32 (x,y) slices of 256 floats
    __shared__ float sh_bot[1024];     // bot2 slice for current x
    __shared__ float sh_top[1024];     // top2 slice for current x
    __shared__ float sh_t[1024];       // t[j][I][U]
    __shared__ float sh_v[256];
    __shared__ int   sh_c[32];

    const int n   = blockIdx.x;
    const int tid = threadIdx.x;

    if (tid < 32) sh_c[tid] = cfg[n * 32 + tid];
    __syncthreads();

    // Gather s: A flat index = m*2 + phys, where m = xy*256 + a*64 + b*16 + cc*4 + d
    for (int m = tid; m < 8192; m += 256)
        sh_s[m] = A[2 * m + sh_c[m >> 8]];

    sh_v[tid] = (tid == 0) ? 1.0f : 0.0f;   // v0 = e_0 (visibility via sync below)

    const float* corr = g_corr + n * NVEC;
    const float  eta  = 0.001f;

    for (int x = 0; x < 8; x++) {
        __syncthreads();   // covers: s-gather (x=0) / prev step2's sh_top,sh_t reads

        // Build bot_x, top_x (+ NN correction). 2048 entries, 8 per thread.
        {
            const float* s0 = sh_s + (x * 4 + 0) * 256;
            const float* s1 = sh_s + (x * 4 + 1) * 256;
            const float* s2 = sh_s + (x * 4 + 2) * 256;
            const float* s3 = sh_s + (x * 4 + 3) * 256;
            #pragma unroll
            for (int q = 0; q < 4; q++) {
                const int m = q * 256 + tid;     // 0..1023
                const int U = m & 3;             // also 'd' for top
                const int j = (m >> 2) & 15;
                const int i = (m >> 6) & 15;
                const int l = i >> 2, L = i & 3;
                const int r = j >> 2, R = j & 3;
                float bv = 0.0f, tv = 0.0f;
                #pragma unroll
                for (int u = 0; u < 4; u++) {
                    bv = fmaf(s0[l * 64 + r * 16 + u],
                              s1[L * 64 + R * 16 + u * 4 + U], bv);
                    tv = fmaf(s2[l * 64 + r * 16 + U * 4 + u],
                              s3[L * 64 + R * 16 + u * 4], tv);
                }
                sh_bot[m] = fmaf(eta, corr[x * 1024 + m],      bv);
                sh_top[m] = fmaf(eta, corr[NB + x * 1024 + m], tv);
            }
        }
        __syncthreads();

        // Step 1: t[j][I][U] = sum_i v[i*16+I] * bot2[i,j,U]
        // thread -> (j = tid>>4, U = (tid>>2)&3, I0 = (tid&3)*4), 4 I's each
        {
            const int j  = tid >> 4;
            const int U  = (tid >> 2) & 3;
            const int I0 = (tid & 3) * 4;
            float t0 = 0, t1 = 0, t2 = 0, t3 = 0;
            #pragma unroll
            for (int i = 0; i < 16; i++) {
                const float  bv = sh_bot[i * 64 + j * 4 + U];
                const float4 v4 = *(const float4*)(sh_v + i * 16 + I0);
                t0 = fmaf(bv, v4.x, t0);
                t1 = fmaf(bv, v4.y, t1);
                t2 = fmaf(bv, v4.z, t2);
                t3 = fmaf(bv, v4.w, t3);
            }
            sh_t[j * 64 + (I0 + 0) * 4 + U] = t0;
            sh_t[j * 64 + (I0 + 1) * 4 + U] = t1;
            sh_t[j * 64 + (I0 + 2) * 4 + U] = t2;
            sh_t[j * 64 + (I0 + 3) * 4 + U] = t3;
        }
        __syncthreads();

        // Step 2: v'[(j,J)] = sum_{I,U} t[j][I][U] * top2[I,J,U]  (both float4 over U)
        float nv = 0.0f;
        {
            const int j = tid >> 4;
            const int J = tid & 15;
            const float4* t4 = (const float4*)(sh_t + j * 64);
            const float4* p4 = (const float4*)sh_top;
            #pragma unroll
            for (int I = 0; I < 16; I++) {
                const float4 tv = t4[I];
                const float4 pv = p4[I * 16 + J];
                nv = fmaf(tv.x, pv.x, nv);
                nv = fmaf(tv.y, pv.y, nv);
                nv = fmaf(tv.z, pv.z, nv);
                nv = fmaf(tv.w, pv.w, nv);
            }
        }
        __syncthreads();
        sh_v[tid] = nv;
    }
    __syncthreads();
    if (tid == 0) out[n] = sh_v[0];
}

// ---------------------------------------------------------------------------
// Launch. Inputs (metadata order): cfg(int32), A, W1, b1, W2, b2 (float32).
// Output: 128 float32.
// ---------------------------------------------------------------------------
extern "C" void kernel_launch(void* const* d_in, const int* in_sizes, int n_in,
                              void* d_out, int out_size)
{
    const int*   cfg = (const int*)  d_in[0];
    const float* A   = (const float*)d_in[1];
    const float* W1  = (const float*)d_in[2];
    const float* b1  = (const float*)d_in[3];
    const float* W2  = (const float*)d_in[4];
    const float* b2  = (const float*)d_in[5];
    float* out = (float*)d_out;

    nn_gemm_kernel<<<128, 256>>>(cfg, W1, b1, W2, b2);
    contract_kernel<<<128, 256>>>(cfg, A, out);
}

// round 2
// speedup vs baseline: 1.3123x; 1.3123x over previous
#include <cuda_runtime.h>

#define NSAMP 128
#define HID   64
#define NCFG  32
#define NVEC  16384
#define NB    8192

// Scratch: corr[n][k] = b2[k] + sum_j h[n][j]*W2[j][k]
__device__ float g_corr[NSAMP * NVEC];   // 8 MB

// ---- packed fp32x2 helpers (Blackwell FFMA2 path; ptxas never auto-fuses) ----
__device__ __forceinline__ unsigned long long pack2(float x, float y) {
    unsigned long long d;
    asm("mov.b64 %0, {%1, %2};" : "=l"(d) : "f"(x), "f"(y));
    return d;
}
__device__ __forceinline__ void unpack2(unsigned long long d, float& x, float& y) {
    asm("mov.b64 {%0, %1}, %2;" : "=f"(x), "=f"(y) : "l"(d));
}
__device__ __forceinline__ unsigned long long fma2(unsigned long long a,
                                                   unsigned long long b,
                                                   unsigned long long c) {
    unsigned long long d;
    asm("fma.rn.f32x2 %0, %1, %2, %3;" : "=l"(d) : "l"(a), "l"(b), "l"(c));
    return d;
}

// ---------------------------------------------------------------------------
// Kernel A: corr = relu(cfg@W1+b1) @ W2 + b2  via packed f32x2 FMAs.
// grid = (64 col-blocks, 8 sample-groups), block = 256 threads.
// Thread owns one output column k for its group's 16 samples.
// Lane packing: {even-j partial, odd-j partial} per 64-bit accumulator.
// ---------------------------------------------------------------------------
__global__ void __launch_bounds__(256) nn_gemm_kernel(
    const int*   __restrict__ cfg,
    const float* __restrict__ W1,
    const float* __restrict__ b1,
    const float* __restrict__ W2,
    const float* __restrict__ b2)
{
    __shared__ float sh_h[16 * HID];   // 4 KB: H rows for this sample group
    const int tid = threadIdx.x;
    const int n0  = blockIdx.y * 16;
    const int k   = blockIdx.x * 256 + tid;

    // H for 16 samples (1024 outputs, 4/thread)
    #pragma unroll
    for (int s = 0; s < 4; s++) {
        const int m  = s * 256 + tid;
        const int ln = m >> 6;
        const int o  = m & 63;
        float acc = b1[o];
        const int* crow = cfg + (n0 + ln) * NCFG;
        #pragma unroll
        for (int i = 0; i < NCFG; i++)
            acc = fmaf((float)crow[i], W1[i * HID + o], acc);
        sh_h[ln * HID + o] = fmaxf(acc, 0.0f);
    }
    __syncthreads();

    unsigned long long acc[16];
    #pragma unroll
    for (int nn = 0; nn < 16; nn++) acc[nn] = 0ull;

    // 8 groups of 4 j-pairs (8 j each). Per group: load 4 packed W2 pairs,
    // then FFMA2 across all 16 samples (16 independent chains -> ILP).
    #pragma unroll
    for (int g = 0; g < 8; g++) {
        unsigned long long wp0 = pack2(W2[(8 * g + 0) * NVEC + k], W2[(8 * g + 1) * NVEC + k]);
        unsigned long long wp1 = pack2(W2[(8 * g + 2) * NVEC + k], W2[(8 * g + 3) * NVEC + k]);
        unsigned long long wp2 = pack2(W2[(8 * g + 4) * NVEC + k], W2[(8 * g + 5) * NVEC + k]);
        unsigned long long wp3 = pack2(W2[(8 * g + 6) * NVEC + k], W2[(8 * g + 7) * NVEC + k]);
        #pragma unroll
        for (int nn = 0; nn < 16; nn++) {
            const ulonglong2* h2 = (const ulonglong2*)(sh_h + nn * HID + 8 * g);
            ulonglong2 ha = h2[0];            // j pairs (8g,8g+1),(8g+2,8g+3)
            ulonglong2 hb = h2[1];            // j pairs (8g+4,..),(8g+6,..)
            acc[nn] = fma2(ha.x, wp0, acc[nn]);
            acc[nn] = fma2(ha.y, wp1, acc[nn]);
            acc[nn] = fma2(hb.x, wp2, acc[nn]);
            acc[nn] = fma2(hb.y, wp3, acc[nn]);
        }
    }

    const float bk = b2[k];
    #pragma unroll
    for (int nn = 0; nn < 16; nn++) {
        float x, y; unpack2(acc[nn], x, y);
        g_corr[(n0 + nn) * NVEC + k] = x + y + bk;   // coalesced
    }
}

// ---------------------------------------------------------------------------
// Kernel B: per-sample contraction + factored transfer-matrix scan.
// grid = 128 (one block per sample), block = 512 threads.
// Dynamic smem layout (floats):
//   [0,8192)      bot2 for ALL x  (8 x 1024)
//   [8192,16384)  top2 for ALL x
//   [16384,24576) gathered s tensor (32 slices x 256)
//   [24576,25600) t scratch
//   [25600,25856) v vector
// All bot/top building happens ONCE before the scan -> scan loop is just
// step1 + step2 with 2 barriers per x.
// ---------------------------------------------------------------------------
__global__ void __launch_bounds__(512) contract_kernel(
    const int*   __restrict__ cfg,
    const float* __restrict__ A,
    float*       __restrict__ out)
{
    extern __shared__ float sm[];
    float* sh_bot = sm;
    float* sh_top = sm + 8192;
    float* sh_s   = sm + 16384;
    float* sh_t   = sm + 24576;
    float* sh_v   = sm + 25600;
    __shared__ int sh_c[32];

    const int n   = blockIdx.x;
    const int tid = threadIdx.x;

    if (tid < 32) sh_c[tid] = cfg[n * 32 + tid];
    __syncthreads();

    // Gather s: A flat = m*2 + phys  (vectorized float2 + select)
    const float2* A2 = (const float2*)A;
    #pragma unroll
    for (int q = 0; q < 16; q++) {
        const int m = q * 512 + tid;
        const float2 a = A2[m];
        sh_s[m] = sh_c[m >> 8] ? a.y : a.x;
    }
    if (tid < 256) sh_v[tid] = (tid == 0) ? 1.0f : 0.0f;
    __syncthreads();

    const float* corr = g_corr + n * NVEC;
    const float  eta  = 0.001f;

    // Build ALL bot2/top2 (2048 groups of 4 U-values, 4 groups/thread)
    #pragma unroll
    for (int q = 0; q < 4; q++) {
        const int g = q * 512 + tid;          // 0..2047
        const int x = g >> 8;
        const int i = (g >> 4) & 15;
        const int j = g & 15;
        const int l = i >> 2, L = i & 3;
        const int r = j >> 2, R = j & 3;
        const float* s0 = sh_s + (x * 4 + 0) * 256;
        const float* s1 = sh_s + (x * 4 + 1) * 256;
        const float* s2 = sh_s + (x * 4 + 2) * 256;
        const float* s3 = sh_s + (x * 4 + 3) * 256;

        // bot[U] = sum_u s0[l,r,u] * s1[L,R,u,U]
        const float4  a0 = *(const float4*)(s0 + l * 64 + r * 16);
        const float4* b4 = (const float4*)(s1 + L * 64 + R * 16);
        const float4 b0 = b4[0], b1v = b4[1], b2v = b4[2], b3v = b4[3];
        float4 bo;
        bo.x = fmaf(a0.x, b0.x, fmaf(a0.y, b1v.x, fmaf(a0.z, b2v.x, a0.w * b3v.x)));
        bo.y = fmaf(a0.x, b0.y, fmaf(a0.y, b1v.y, fmaf(a0.z, b2v.y, a0.w * b3v.y)));
        bo.z = fmaf(a0.x, b0.z, fmaf(a0.y, b1v.z, fmaf(a0.z, b2v.z, a0.w * b3v.z)));
        bo.w = fmaf(a0.x, b0.w, fmaf(a0.y, b1v.w, fmaf(a0.z, b2v.w, a0.w * b3v.w)));

        // top[dd] = sum_u s2[l,r,dd,u] * s3[L,R,u,0]
        const float4* c4 = (const float4*)(s2 + l * 64 + r * 16);
        const float4 c0 = c4[0], c1 = c4[1], c2 = c4[2], c3 = c4[3];
        const float e0 = s3[L * 64 + R * 16 + 0];
        const float e1 = s3[L * 64 + R * 16 + 4];
        const float e2 = s3[L * 64 + R * 16 + 8];
        const float e3 = s3[L * 64 + R * 16 + 12];
        float4 to;
        to.x = fmaf(c0.x, e0, fmaf(c0.y, e1, fmaf(c0.z, e2, c0.w * e3)));
        to.y = fmaf(c1.x, e0, fmaf(c1.y, e1, fmaf(c1.z, e2, c1.w * e3)));
        to.z = fmaf(c2.x, e0, fmaf(c2.y, e1, fmaf(c2.z, e2, c2.w * e3)));
        to.w = fmaf(c3.x, e0, fmaf(c3.y, e1, fmaf(c3.z, e2, c3.w * e3)));

        const int mbase = x * 1024 + i * 64 + j * 4;
        const float4 cb = *(const float4*)(corr + mbase);
        const float4 ct = *(const float4*)(corr + NB + mbase);
        float4 ob, ot;
        ob.x = fmaf(eta, cb.x, bo.x); ob.y = fmaf(eta, cb.y, bo.y);
        ob.z = fmaf(eta, cb.z, bo.z); ob.w = fmaf(eta, cb.w, bo.w);
        ot.x = fmaf(eta, ct.x, to.x); ot.y = fmaf(eta, ct.y, to.y);
        ot.z = fmaf(eta, ct.z, to.z); ot.w = fmaf(eta, ct.w, to.w);
        *(float4*)(sh_bot + mbase) = ob;
        *(float4*)(sh_top + mbase) = ot;
    }
    __syncthreads();

    // Scan: 8 x-steps, 2 barriers each
    #pragma unroll 1
    for (int x = 0; x < 8; x++) {
        const float* bt = sh_bot + x * 1024;

        // step1: t[j][I][U] = sum_i v[i*16+I] * bot[i,j,U]
        // thread -> (j = tid>>5 [warp-uniform], U = (tid>>3)&3, I pair)
        {
            const int j   = tid >> 5;
            const int rem = tid & 31;
            const int U   = rem >> 3;
            const int I0  = (rem & 7) * 2;
            float t0 = 0.f, t1 = 0.f;
            #pragma unroll
            for (int i = 0; i < 16; i++) {
                const float  bv = bt[i * 64 + j * 4 + U];          // broadcast in warp
                const float2 v2 = *(const float2*)(sh_v + i * 16 + I0);
                t0 = fmaf(bv, v2.x, t0);
                t1 = fmaf(bv, v2.y, t1);
            }
            sh_t[j * 64 + I0 * 4 + U]       = t0;
            sh_t[j * 64 + (I0 + 1) * 4 + U] = t1;
        }
        __syncthreads();

        // step2: v'[(j,J)] = sum_{I,U} t[j][I][U] * top[I,J,U]
        // two threads per output (I split 8+8), combined via shfl
        {
            const int o    = tid >> 1;
            const int j    = o >> 4;
            const int J    = o & 15;
            const int Ib   = (tid & 1) * 8;
            const float4* t4 = (const float4*)(sh_t + j * 64);
            const float4* p4 = (const float4*)(sh_top + x * 1024);
            float nv = 0.f;
            #pragma unroll
            for (int ii = 0; ii < 8; ii++) {
                const int I = Ib + ii;
                const float4 tv = t4[I];
                const float4 pv = p4[I * 16 + J];
                nv = fmaf(tv.x, pv.x, nv);
                nv = fmaf(tv.y, pv.y, nv);
                nv = fmaf(tv.z, pv.z, nv);
                nv = fmaf(tv.w, pv.w, nv);
            }
            nv += __shfl_xor_sync(0xffffffffu, nv, 1);
            if ((tid & 1) == 0) sh_v[o] = nv;
        }
        __syncthreads();
    }

    if (tid == 0) out[n] = sh_v[0];
}

// ---------------------------------------------------------------------------
extern "C" void kernel_launch(void* const* d_in, const int* in_sizes, int n_in,
                              void* d_out, int out_size)
{
    const int*   cfg = (const int*)  d_in[0];
    const float* A   = (const float*)d_in[1];
    const float* W1  = (const float*)d_in[2];
    const float* b1  = (const float*)d_in[3];
    const float* W2  = (const float*)d_in[4];
    const float* b2  = (const float*)d_in[5];
    float* out = (float*)d_out;

    cudaFuncSetAttribute(contract_kernel,
                         cudaFuncAttributeMaxDynamicSharedMemorySize, 25856 * 4);

    nn_gemm_kernel<<<dim3(64, 8), 256>>>(cfg, W1, b1, W2, b2);
    contract_kernel<<<128, 512, 25856 * 4>>>(cfg, A, out);
}

// round 6
// speedup vs baseline: 1.4939x; 1.1383x over previous
#include <cuda_runtime.h>

#define NSAMP 128
#define HID   64
#define NCFG  32
#define NVEC  16384
#define NB    8192

__device__ float g_corr[NSAMP * NVEC];   // 8 MB scratch

// ---- packed fp32x2 helpers ----
__device__ __forceinline__ unsigned long long pack2(float x, float y) {
    unsigned long long d;
    asm("mov.b64 %0, {%1, %2};" : "=l"(d) : "f"(x), "f"(y));
    return d;
}
__device__ __forceinline__ void unpack2(unsigned long long d, float& x, float& y) {
    asm("mov.b64 {%0, %1}, %2;" : "=f"(x), "=f"(y) : "l"(d));
}
__device__ __forceinline__ unsigned long long fma2(unsigned long long a,
                                                   unsigned long long b,
                                                   unsigned long long c) {
    unsigned long long d;
    asm("fma.rn.f32x2 %0, %1, %2, %3;" : "=l"(d) : "l"(a), "l"(b), "l"(c));
    return d;
}

// ---------------------------------------------------------------------------
// Kernel A: corr = relu(cfg@W1+b1) @ W2 + b2.
// grid = (32 k-blocks, 8 sample-groups), block = 128 threads.
// Thread owns 4 consecutive k for 16 samples. acc lanes = (k-pair).
// H stored duplicated {h,h} so one LDS.128 serves 4 FFMA2.
// ---------------------------------------------------------------------------
__global__ void __launch_bounds__(128) nn_gemm_kernel(
    const int*   __restrict__ cfg,
    const float* __restrict__ W1,
    const float* __restrict__ b1,
    const float* __restrict__ W2,
    const float* __restrict__ b2)
{
    __shared__ unsigned long long sh_hd[16 * HID];   // 8 KB, {h,h} per entry
    const int tid = threadIdx.x;
    const int n0  = blockIdx.y * 16;
    const int k4  = blockIdx.x * 512 + tid * 4;

    // H for 16 samples (1024 outputs, 8/thread), stored duplicated
    #pragma unroll
    for (int s8 = 0; s8 < 8; s8++) {
        const int m  = s8 * 128 + tid;
        const int ln = m >> 6;
        const int o  = m & 63;
        float acc = b1[o];
        const int* crow = cfg + (n0 + ln) * NCFG;
        #pragma unroll
        for (int i = 0; i < NCFG; i++)
            acc = fmaf((float)crow[i], W1[i * HID + o], acc);
        const float h = fmaxf(acc, 0.0f);
        sh_hd[ln * HID + o] = pack2(h, h);
    }
    __syncthreads();

    unsigned long long acc[32];   // acc[s*2 + p], p = k-pair (k4+0,1)/(k4+2,3)
    #pragma unroll
    for (int q = 0; q < 32; q++) acc[q] = 0ull;

    #pragma unroll 4
    for (int jq = 0; jq < 16; jq++) {
        const int j0 = jq * 4;
        // W2 rows j0..j0+3, 4 consecutive k each (LDG.128)
        const float4 w0 = *(const float4*)(W2 + (j0 + 0) * NVEC + k4);
        const float4 w1 = *(const float4*)(W2 + (j0 + 1) * NVEC + k4);
        const float4 w2 = *(const float4*)(W2 + (j0 + 2) * NVEC + k4);
        const float4 w3 = *(const float4*)(W2 + (j0 + 3) * NVEC + k4);
        const unsigned long long w0lo = pack2(w0.x, w0.y), w0hi = pack2(w0.z, w0.w);
        const unsigned long long w1lo = pack2(w1.x, w1.y), w1hi = pack2(w1.z, w1.w);
        const unsigned long long w2lo = pack2(w2.x, w2.y), w2hi = pack2(w2.z, w2.w);
        const unsigned long long w3lo = pack2(w3.x, w3.y), w3hi = pack2(w3.z, w3.w);

        #pragma unroll
        for (int s = 0; s < 16; s++) {
            const ulonglong2 hd01 = *(const ulonglong2*)(sh_hd + s * HID + j0);
            const ulonglong2 hd23 = *(const ulonglong2*)(sh_hd + s * HID + j0 + 2);
            unsigned long long a0 = acc[s * 2 + 0];
            unsigned long long a1 = acc[s * 2 + 1];
            a0 = fma2(hd01.x, w0lo, a0);  a1 = fma2(hd01.x, w0hi, a1);
            a0 = fma2(hd01.y, w1lo, a0);  a1 = fma2(hd01.y, w1hi, a1);
            a0 = fma2(hd23.x, w2lo, a0);  a1 = fma2(hd23.x, w2hi, a1);
            a0 = fma2(hd23.y, w3lo, a0);  a1 = fma2(hd23.y, w3hi, a1);
            acc[s * 2 + 0] = a0;
            acc[s * 2 + 1] = a1;
        }
    }

    const float4 bk = *(const float4*)(b2 + k4);
    #pragma unroll
    for (int s = 0; s < 16; s++) {
        float4 r;
        unpack2(acc[s * 2 + 0], r.x, r.y);
        unpack2(acc[s * 2 + 1], r.z, r.w);
        r.x += bk.x; r.y += bk.y; r.z += bk.z; r.w += bk.w;
        *(float4*)(g_corr + (n0 + s) * NVEC + k4) = r;   // coalesced
    }
}

// ---------------------------------------------------------------------------
// Kernel B: per-sample contraction + scan, 1 block/sample, 512 threads.
// Scan mapping: warp w owns output row j=w. Step1 -> warp-private t strip
// (__syncwarp only); step2 consumes it; v ping-pong => ONE __syncthreads/x.
// smem floats: bot[8192] top[8192] s[8192] t[1024] v0[256] v1[256]
// ---------------------------------------------------------------------------
#define SMEM_FLOATS (8192 + 8192 + 8192 + 1024 + 256 + 256)

__global__ void __launch_bounds__(512) contract_kernel(
    const int*   __restrict__ cfg,
    const float* __restrict__ A,
    float*       __restrict__ out)
{
    extern __shared__ float sm[];
    float* sh_bot = sm;
    float* sh_top = sm + 8192;
    float* sh_s   = sm + 16384;
    float* sh_t   = sm + 24576;
    float* sh_v0  = sm + 25600;
    float* sh_v1  = sm + 25856;
    __shared__ int sh_c[32];

    const int n   = blockIdx.x;
    const int tid = threadIdx.x;

    if (tid < 32) sh_c[tid] = cfg[n * 32 + tid];
    __syncthreads();

    // Gather s: A flat = m*2 + phys
    const float2* A2 = (const float2*)A;
    #pragma unroll
    for (int q = 0; q < 16; q++) {
        const int m = q * 512 + tid;
        const float2 a = A2[m];
        sh_s[m] = sh_c[m >> 8] ? a.y : a.x;
    }
    if (tid < 256) sh_v0[tid] = (tid == 0) ? 1.0f : 0.0f;
    __syncthreads();

    const float* corr = g_corr + n * NVEC;
    const float  eta  = 0.001f;

    // Build ALL bot2/top2 (+ corr)
    #pragma unroll
    for (int q = 0; q < 4; q++) {
        const int g = q * 512 + tid;
        const int x = g >> 8;
        const int i = (g >> 4) & 15;
        const int j = g & 15;
        const int l = i >> 2, L = i & 3;
        const int r = j >> 2, R = j & 3;
        const float* s0 = sh_s + (x * 4 + 0) * 256;
        const float* s1 = sh_s + (x * 4 + 1) * 256;
        const float* s2 = sh_s + (x * 4 + 2) * 256;
        const float* s3 = sh_s + (x * 4 + 3) * 256;

        const float4  a0 = *(const float4*)(s0 + l * 64 + r * 16);
        const float4* b4 = (const float4*)(s1 + L * 64 + R * 16);
        const float4 b0 = b4[0], b1v = b4[1], b2v = b4[2], b3v = b4[3];
        float4 bo;
        bo.x = fmaf(a0.x, b0.x, fmaf(a0.y, b1v.x, fmaf(a0.z, b2v.x, a0.w * b3v.x)));
        bo.y = fmaf(a0.x, b0.y, fmaf(a0.y, b1v.y, fmaf(a0.z, b2v.y, a0.w * b3v.y)));
        bo.z = fmaf(a0.x, b0.z, fmaf(a0.y, b1v.z, fmaf(a0.z, b2v.z, a0.w * b3v.z)));
        bo.w = fmaf(a0.x, b0.w, fmaf(a0.y, b1v.w, fmaf(a0.z, b2v.w, a0.w * b3v.w)));

        const float4* c4 = (const float4*)(s2 + l * 64 + r * 16);
        const float4 c0 = c4[0], c1 = c4[1], c2 = c4[2], c3 = c4[3];
        const float e0 = s3[L * 64 + R * 16 + 0];
        const float e1 = s3[L * 64 + R * 16 + 4];
        const float e2 = s3[L * 64 + R * 16 + 8];
        const float e3 = s3[L * 64 + R * 16 + 12];
        float4 to;
        to.x = fmaf(c0.x, e0, fmaf(c0.y, e1, fmaf(c0.z, e2, c0.w * e3)));
        to.y = fmaf(c1.x, e0, fmaf(c1.y, e1, fmaf(c1.z, e2, c1.w * e3)));
        to.z = fmaf(c2.x, e0, fmaf(c2.y, e1, fmaf(c2.z, e2, c2.w * e3)));
        to.w = fmaf(c3.x, e0, fmaf(c3.y, e1, fmaf(c3.z, e2, c3.w * e3)));

        const int mbase = x * 1024 + i * 64 + j * 4;
        const float4 cb = *(const float4*)(corr + mbase);
        const float4 ct = *(const float4*)(corr + NB + mbase);
        float4 ob, ot;
        ob.x = fmaf(eta, cb.x, bo.x); ob.y = fmaf(eta, cb.y, bo.y);
        ob.z = fmaf(eta, cb.z, bo.z); ob.w = fmaf(eta, cb.w, bo.w);
        ot.x = fmaf(eta, ct.x, to.x); ot.y = fmaf(eta, ct.y, to.y);
        ot.z = fmaf(eta, ct.z, to.z); ot.w = fmaf(eta, ct.w, to.w);
        *(float4*)(sh_bot + mbase) = ob;
        *(float4*)(sh_top + mbase) = ot;
    }
    __syncthreads();

    // Scan: warp w <-> row j=w; ONE block barrier per x
    const int w    = tid >> 5;
    const int lane = tid & 31;
    const int I1   = lane >> 1;          // step1: this lane's I
    const int Up   = (lane & 1) * 2;     // step1: U pair base
    const int J2   = lane >> 1;          // step2: this lane's J
    const int Ib   = (lane & 1) * 8;     // step2: I half

    #pragma unroll 1
    for (int x = 0; x < 8; x++) {
        const float* vcur  = (x & 1) ? sh_v1 : sh_v0;
        float*       vnext = (x & 1) ? sh_v0 : sh_v1;
        const float* bt = sh_bot + x * 1024;
        const float* tp = sh_top + x * 1024;

        // step1: t[I][Up..Up+1] = sum_i vcur[i*16+I] * bot[i*64 + w*4 + Up..]
        {
            float t0 = 0.f, t1 = 0.f;
            #pragma unroll
            for (int i = 0; i < 16; i++) {
                const float2 bv = *(const float2*)(bt + i * 64 + w * 4 + Up);
                const float  vv = vcur[i * 16 + I1];
                t0 = fmaf(vv, bv.x, t0);
                t1 = fmaf(vv, bv.y, t1);
            }
            *(float2*)(sh_t + w * 64 + I1 * 4 + Up) = make_float2(t0, t1);
        }
        __syncwarp();

        // step2: v'[w*16+J2] = sum_{I,U} t[I][U] * top[I*64 + J2*4 + U]
        {
            float nv = 0.f;
            #pragma unroll
            for (int ii = 0; ii < 8; ii++) {
                const int I = Ib + ii;
                const float4 tv = *(const float4*)(sh_t + w * 64 + I * 4);
                const float4 pv = *(const float4*)(tp + I * 64 + J2 * 4);
                nv = fmaf(tv.x, pv.x, nv);
                nv = fmaf(tv.y, pv.y, nv);
                nv = fmaf(tv.z, pv.z, nv);
                nv = fmaf(tv.w, pv.w, nv);
            }
            nv += __shfl_xor_sync(0xffffffffu, nv, 1);
            if ((lane & 1) == 0) vnext[w * 16 + J2] = nv;
        }
        __syncthreads();
    }

    if (tid == 0) out[n] = sh_v0[0];   // x=7 wrote sh_v0
}

// ---------------------------------------------------------------------------
extern "C" void kernel_launch(void* const* d_in, const int* in_sizes, int n_in,
                              void* d_out, int out_size)
{
    const int*   cfg = (const int*)  d_in[0];
    const float* A   = (const float*)d_in[1];
    const float* W1  = (const float*)d_in[2];
    const float* b1  = (const float*)d_in[3];
    const float* W2  = (const float*)d_in[4];
    const float* b2  = (const float*)d_in[5];
    float* out = (float*)d_out;

    cudaFuncSetAttribute(contract_kernel,
                         cudaFuncAttributeMaxDynamicSharedMemorySize,
                         SMEM_FLOATS * 4);

    nn_gemm_kernel<<<dim3(32, 8), 128>>>(cfg, W1, b1, W2, b2);
    contract_kernel<<<128, 512, SMEM_FLOATS * 4>>>(cfg, A, out);
}

// round 7
// speedup vs baseline: 1.6437x; 1.1003x over previous
#include <cuda_runtime.h>
#include <cstdint>

#define HID   64
#define NVEC  16384
#define NB    8192

// bot/top (s-product + eta*(h@W2+b2)) for all samples: bt[n][k], k<8192 bot, >=8192 top
__device__ float g_bt[128 * NVEC];   // 8 MB

// ---- packed fp32x2 helpers ----
__device__ __forceinline__ unsigned long long pack2(float x, float y) {
    unsigned long long d;
    asm("mov.b64 %0, {%1, %2};" : "=l"(d) : "f"(x), "f"(y));
    return d;
}
__device__ __forceinline__ void unpack2(unsigned long long d, float& x, float& y) {
    asm("mov.b64 {%0, %1}, %2;" : "=f"(x), "=f"(y) : "l"(d));
}
__device__ __forceinline__ unsigned long long fma2(unsigned long long a,
                                                   unsigned long long b,
                                                   unsigned long long c) {
    unsigned long long d;
    asm("fma.rn.f32x2 %0, %1, %2, %3;" : "=l"(d) : "l"(a), "l"(b), "l"(c));
    return d;
}

__device__ __forceinline__ void cp_async16(uint32_t dst, const void* src) {
    asm volatile("cp.async.cg.shared.global [%0], [%1], 16;" :: "r"(dst), "l"(src));
}

// ---------------------------------------------------------------------------
// Kernel A: fused GEMM + bot/top build.
// grid = (16 slabs, 8 sample-groups) = 128 blocks (one wave), 256 threads.
// slab < 8:  x = slab,   bot half (k in [x*1024, x*1024+1024))
// slab >= 8: x = slab-8, top half (k-8192 likewise)
// Thread owns k4 = slab*1024 + tid*4 (4 consecutive k) for 16 samples.
// Writes g_bt[n][k4..k4+3] = s-product + eta*(h@W2 + b2).
// ---------------------------------------------------------------------------
__global__ void __launch_bounds__(256) fused_gemm_build(
    const int*   __restrict__ cfg,
    const float* __restrict__ A,
    const float* __restrict__ W1,
    const float* __restrict__ b1,
    const float* __restrict__ W2,
    const float* __restrict__ b2)
{
    __shared__ unsigned long long sh_hd[16 * HID];  // 8 KB, {h,h} duplicated
    __shared__ float sh_s[16 * 512];                // 32 KB: per sample, 2 slices x 256
    __shared__ int   sh_c[32];                      // cfg for (sample, slice)

    const int tid   = threadIdx.x;
    const int slab  = blockIdx.x;       // 0..15
    const int n0    = blockIdx.y * 16;
    const int xx    = slab & 7;
    const int isTop = slab >> 3;
    const int ybase = isTop * 2;        // bot: y=0,1 ; top: y=2,3
    const int k4    = slab * 1024 + tid * 4;

    if (tid < 32) {
        const int s = tid >> 1, sl = tid & 1;
        sh_c[tid] = cfg[(n0 + s) * 32 + xx * 4 + ybase + sl];
    }
    __syncthreads();

    // Gather the two needed slices per sample (select phys by cfg)
    const float2* A2 = (const float2*)A;
    #pragma unroll
    for (int q = 0; q < 32; q++) {
        const int m   = q * 256 + tid;       // 0..8191
        const int s   = m >> 9;
        const int sl  = (m >> 8) & 1;
        const int idx = m & 255;
        const float2 a = A2[(xx * 4 + ybase + sl) * 256 + idx];
        sh_s[m] = sh_c[(s << 1) | sl] ? a.y : a.x;
    }

    // H = relu(cfg@W1+b1) for this group's 16 samples, stored duplicated
    #pragma unroll
    for (int q = 0; q < 4; q++) {
        const int m  = q * 256 + tid;
        const int ln = m >> 6;
        const int o  = m & 63;
        float acc = b1[o];
        const int* crow = cfg + (n0 + ln) * 32;
        #pragma unroll
        for (int i = 0; i < 32; i++)
            acc = fmaf((float)crow[i], W1[i * HID + o], acc);
        const float h = fmaxf(acc, 0.0f);
        sh_hd[ln * HID + o] = pack2(h, h);
    }
    __syncthreads();

    // GEMM: acc[s*2+p] packed over k-pairs
    unsigned long long acc[32];
    #pragma unroll
    for (int q = 0; q < 32; q++) acc[q] = 0ull;

    #pragma unroll 4
    for (int jq = 0; jq < 16; jq++) {
        const int j0 = jq * 4;
        const float4 w0 = *(const float4*)(W2 + (j0 + 0) * NVEC + k4);
        const float4 w1 = *(const float4*)(W2 + (j0 + 1) * NVEC + k4);
        const float4 w2 = *(const float4*)(W2 + (j0 + 2) * NVEC + k4);
        const float4 w3 = *(const float4*)(W2 + (j0 + 3) * NVEC + k4);
        const unsigned long long w0lo = pack2(w0.x, w0.y), w0hi = pack2(w0.z, w0.w);
        const unsigned long long w1lo = pack2(w1.x, w1.y), w1hi = pack2(w1.z, w1.w);
        const unsigned long long w2lo = pack2(w2.x, w2.y), w2hi = pack2(w2.z, w2.w);
        const unsigned long long w3lo = pack2(w3.x, w3.y), w3hi = pack2(w3.z, w3.w);

        #pragma unroll
        for (int s = 0; s < 16; s++) {
            const ulonglong2 hd01 = *(const ulonglong2*)(sh_hd + s * HID + j0);
            const ulonglong2 hd23 = *(const ulonglong2*)(sh_hd + s * HID + j0 + 2);
            unsigned long long a0 = acc[s * 2 + 0];
            unsigned long long a1 = acc[s * 2 + 1];
            a0 = fma2(hd01.x, w0lo, a0);  a1 = fma2(hd01.x, w0hi, a1);
            a0 = fma2(hd01.y, w1lo, a0);  a1 = fma2(hd01.y, w1hi, a1);
            a0 = fma2(hd23.x, w2lo, a0);  a1 = fma2(hd23.x, w2hi, a1);
            a0 = fma2(hd23.y, w3lo, a0);  a1 = fma2(hd23.y, w3hi, a1);
            acc[s * 2 + 0] = a0;
            acc[s * 2 + 1] = a1;
        }
    }

    // Epilogue: add s-product, write bt
    const int i = tid >> 4, j = tid & 15;
    const int l = i >> 2, L = i & 3, r = j >> 2, R = j & 3;
    const float4 bk  = *(const float4*)(b2 + k4);
    const float  eta = 0.001f;

    if (!isTop) {
        #pragma unroll
        for (int s = 0; s < 16; s++) {
            float4 cr;
            unpack2(acc[s * 2 + 0], cr.x, cr.y);
            unpack2(acc[s * 2 + 1], cr.z, cr.w);
            cr.x += bk.x; cr.y += bk.y; cr.z += bk.z; cr.w += bk.w;

            const float* sa = sh_s + s * 512;        // s0 slice
            const float* sb = sh_s + s * 512 + 256;  // s1 slice
            const float4  a0 = *(const float4*)(sa + l * 64 + r * 16);
            const float4* b4 = (const float4*)(sb + L * 64 + R * 16);
            const float4 b0 = b4[0], b1v = b4[1], b2v = b4[2], b3v = b4[3];
            float4 o4;
            o4.x = fmaf(a0.x, b0.x, fmaf(a0.y, b1v.x, fmaf(a0.z, b2v.x, fmaf(a0.w, b3v.x, eta * cr.x))));
            o4.y = fmaf(a0.x, b0.y, fmaf(a0.y, b1v.y, fmaf(a0.z, b2v.y, fmaf(a0.w, b3v.y, eta * cr.y))));
            o4.z = fmaf(a0.x, b0.z, fmaf(a0.y, b1v.z, fmaf(a0.z, b2v.z, fmaf(a0.w, b3v.z, eta * cr.z))));
            o4.w = fmaf(a0.x, b0.w, fmaf(a0.y, b1v.w, fmaf(a0.z, b2v.w, fmaf(a0.w, b3v.w, eta * cr.w))));
            *(float4*)(g_bt + (n0 + s) * NVEC + k4) = o4;
        }
    } else {
        #pragma unroll
        for (int s = 0; s < 16; s++) {
            float4 cr;
            unpack2(acc[s * 2 + 0], cr.x, cr.y);
            unpack2(acc[s * 2 + 1], cr.z, cr.w);
            cr.x += bk.x; cr.y += bk.y; cr.z += bk.z; cr.w += bk.w;

            const float* sa = sh_s + s * 512;        // s2 slice
            const float* sb = sh_s + s * 512 + 256;  // s3 slice
            const float4* c4 = (const float4*)(sa + l * 64 + r * 16);
            const float4 c0 = c4[0], c1 = c4[1], c2 = c4[2], c3 = c4[3];
            const float e0 = sb[L * 64 + R * 16 + 0];
            const float e1 = sb[L * 64 + R * 16 + 4];
            const float e2 = sb[L * 64 + R * 16 + 8];
            const float e3 = sb[L * 64 + R * 16 + 12];
            float4 o4;
            o4.x = fmaf(c0.x, e0, fmaf(c0.y, e1, fmaf(c0.z, e2, fmaf(c0.w, e3, eta * cr.x))));
            o4.y = fmaf(c1.x, e0, fmaf(c1.y, e1, fmaf(c1.z, e2, fmaf(c1.w, e3, eta * cr.y))));
            o4.z = fmaf(c2.x, e0, fmaf(c2.y, e1, fmaf(c2.z, e2, fmaf(c2.w, e3, eta * cr.z))));
            o4.w = fmaf(c3.x, e0, fmaf(c3.y, e1, fmaf(c3.z, e2, fmaf(c3.w, e3, eta * cr.w))));
            *(float4*)(g_bt + (n0 + s) * NVEC + k4) = o4;
        }
    }
}

// ---------------------------------------------------------------------------
// Kernel B: scan only. 128 blocks x 512 threads, cp.async double-buffered
// bt tiles (bot 1024 + top 1024 floats per x), 1 block barrier per x.
// ---------------------------------------------------------------------------
__global__ void __launch_bounds__(512) scan_kernel(float* __restrict__ out)
{
    __shared__ float buf[2][2048];     // [x&1][bot:0..1023 | top:1024..2047]
    __shared__ float sh_t[1024];
    __shared__ float sh_v0[256], sh_v1[256];

    const int n   = blockIdx.x;
    const int tid = threadIdx.x;
    const float* src = g_bt + n * NVEC;

    const int half = tid >> 8;          // 0: bot, 1: top
    const int e4   = (tid & 255) * 4;   // float offset within tile

    // prefetch x=0 and x=1
    cp_async16((uint32_t)__cvta_generic_to_shared(&buf[0][half * 1024 + e4]),
               src + 0 * 1024 + half * 8192 + e4);
    asm volatile("cp.async.commit_group;");
    cp_async16((uint32_t)__cvta_generic_to_shared(&buf[1][half * 1024 + e4]),
               src + 1 * 1024 + half * 8192 + e4);
    asm volatile("cp.async.commit_group;");

    if (tid < 256) sh_v0[tid] = (tid == 0) ? 1.0f : 0.0f;

    const int w    = tid >> 5;
    const int lane = tid & 31;
    const int I1   = lane >> 1;
    const int Up   = (lane & 1) * 2;
    const int J2   = lane >> 1;
    const int Ib   = (lane & 1) * 8;

    #pragma unroll 1
    for (int x = 0; x < 8; x++) {
        asm volatile("cp.async.wait_group 1;");
        __syncthreads();   // tile x ready; v from previous step visible

        const float* vcur  = (x & 1) ? sh_v1 : sh_v0;
        float*       vnext = (x & 1) ? sh_v0 : sh_v1;
        const float* bt = buf[x & 1];
        const float* tp = buf[x & 1] + 1024;

        // step1: t[I][Up..] = sum_i vcur[i*16+I] * bot[i*64 + w*4 + Up..]
        {
            float t0 = 0.f, t1 = 0.f;
            #pragma unroll
            for (int i = 0; i < 16; i++) {
                const float2 bv = *(const float2*)(bt + i * 64 + w * 4 + Up);
                const float  vv = vcur[i * 16 + I1];
                t0 = fmaf(vv, bv.x, t0);
                t1 = fmaf(vv, bv.y, t1);
            }
            *(float2*)(sh_t + w * 64 + I1 * 4 + Up) = make_float2(t0, t1);
        }
        __syncwarp();

        // step2: v'[w*16+J2] = sum_{I,U} t[I][U] * top[I*64 + J2*4 + U]
        {
            float nv = 0.f;
            #pragma unroll
            for (int ii = 0; ii < 8; ii++) {
                const int I = Ib + ii;
                const float4 tv = *(const float4*)(sh_t + w * 64 + I * 4);
                const float4 pv = *(const float4*)(tp + I * 64 + J2 * 4);
                nv = fmaf(tv.x, pv.x, nv);
                nv = fmaf(tv.y, pv.y, nv);
                nv = fmaf(tv.z, pv.z, nv);
                nv = fmaf(tv.w, pv.w, nv);
            }
            nv += __shfl_xor_sync(0xffffffffu, nv, 1);
            if ((lane & 1) == 0) vnext[w * 16 + J2] = nv;
        }
        __syncthreads();   // done reading buf[x&1] and vcur

        if (x < 6) {
            cp_async16((uint32_t)__cvta_generic_to_shared(&buf[x & 1][half * 1024 + e4]),
                       src + (x + 2) * 1024 + half * 8192 + e4);
        }
        asm volatile("cp.async.commit_group;");   // empty group ok, keeps count aligned
    }

    if (tid == 0) out[n] = sh_v0[0];   // x=7 wrote sh_v0
}

// ---------------------------------------------------------------------------
extern "C" void kernel_launch(void* const* d_in, const int* in_sizes, int n_in,
                              void* d_out, int out_size)
{
    const int*   cfg = (const int*)  d_in[0];
    const float* A   = (const float*)d_in[1];
    const float* W1  = (const float*)d_in[2];
    const float* b1  = (const float*)d_in[3];
    const float* W2  = (const float*)d_in[4];
    const float* b2  = (const float*)d_in[5];
    float* out = (float*)d_out;

    fused_gemm_build<<<dim3(16, 8), 256>>>(cfg, A, W1, b1, W2, b2);
    scan_kernel<<<128, 512>>>(out);
}

// round 9
// speedup vs baseline: 1.7214x; 1.0472x over previous
#include <cuda_runtime.h>
#include <cstdint>

#define HID   64
#define NVEC  16384
#define NB    8192

// bot/top (s-product + eta*(h@W2+b2)): g_bt[n][k], k<8192 bot, >=8192 top
__device__ float g_bt[128 * NVEC];   // 8 MB

// ---- packed fp32x2 helpers ----
__device__ __forceinline__ unsigned long long pack2(float x, float y) {
    unsigned long long d;
    asm("mov.b64 %0, {%1, %2};" : "=l"(d) : "f"(x), "f"(y));
    return d;
}
__device__ __forceinline__ void unpack2(unsigned long long d, float& x, float& y) {
    asm("mov.b64 {%0, %1}, %2;" : "=f"(x), "=f"(y) : "l"(d));
}
__device__ __forceinline__ unsigned long long fma2(unsigned long long a,
                                                   unsigned long long b,
                                                   unsigned long long c) {
    unsigned long long d;
    asm("fma.rn.f32x2 %0, %1, %2, %3;" : "=l"(d) : "l"(a), "l"(b), "l"(c));
    return d;
}

__device__ __forceinline__ void cp_async16(uint32_t dst, const void* src) {
    asm volatile("cp.async.cg.shared.global [%0], [%1], 16;" :: "r"(dst), "l"(src));
}

// ---------------------------------------------------------------------------
// Kernel A: fused GEMM + bot/top build.
// grid = (16 slabs, 8 sample-groups) = 128 blocks (one wave), 512 threads.
// Thread owns k2 = slab*1024 + tid*2 (2 consecutive k) for 16 samples.
// ---------------------------------------------------------------------------
__global__ void __launch_bounds__(512) fused_gemm_build(
    const int*   __restrict__ cfg,
    const float* __restrict__ A,
    const float* __restrict__ W1,
    const float* __restrict__ b1,
    const float* __restrict__ W2,
    const float* __restrict__ b2)
{
    __shared__ unsigned long long sh_hd[16 * HID];  // 8 KB, {h,h} duplicated
    __shared__ float sh_s[16 * 512];                // 32 KB: per sample, 2 slices x 256
    __shared__ int   sh_c[32];

    const int tid   = threadIdx.x;
    const int slab  = blockIdx.x;       // 0..15
    const int n0    = blockIdx.y * 16;
    const int xx    = slab & 7;
    const int isTop = slab >> 3;
    const int ybase = isTop * 2;        // bot: y=0,1 ; top: y=2,3
    const int k2    = slab * 1024 + tid * 2;

    if (tid < 32) {
        const int s = tid >> 1, sl = tid & 1;
        sh_c[tid] = cfg[(n0 + s) * 32 + xx * 4 + ybase + sl];
    }
    __syncthreads();

    // Gather the two needed slices per sample
    const float2* A2 = (const float2*)A;
    #pragma unroll
    for (int q = 0; q < 16; q++) {
        const int m   = q * 512 + tid;       // 0..8191
        const int s   = m >> 9;
        const int sl  = (m >> 8) & 1;
        const int idx = m & 255;
        const float2 a = A2[(xx * 4 + ybase + sl) * 256 + idx];
        sh_s[m] = sh_c[(s << 1) | sl] ? a.y : a.x;
    }

    // H = relu(cfg@W1+b1), 1024 outputs, 2/thread, stored duplicated
    #pragma unroll
    for (int q = 0; q < 2; q++) {
        const int m  = q * 512 + tid;
        const int ln = m >> 6;
        const int o  = m & 63;
        float acc = b1[o];
        const int* crow = cfg + (n0 + ln) * 32;
        #pragma unroll
        for (int i = 0; i < 32; i++)
            acc = fmaf((float)crow[i], W1[i * HID + o], acc);
        const float h = fmaxf(acc, 0.0f);
        sh_hd[ln * HID + o] = pack2(h, h);
    }
    __syncthreads();

    // GEMM: one packed accumulator per sample (k-pair in lanes)
    unsigned long long acc[16];
    #pragma unroll
    for (int q = 0; q < 16; q++) acc[q] = 0ull;

    #pragma unroll 4
    for (int jq = 0; jq < 16; jq++) {
        const int j0 = jq * 4;
        const float2 w0f = *(const float2*)(W2 + (j0 + 0) * NVEC + k2);
        const float2 w1f = *(const float2*)(W2 + (j0 + 1) * NVEC + k2);
        const float2 w2f = *(const float2*)(W2 + (j0 + 2) * NVEC + k2);
        const float2 w3f = *(const float2*)(W2 + (j0 + 3) * NVEC + k2);
        const unsigned long long w0 = pack2(w0f.x, w0f.y);
        const unsigned long long w1 = pack2(w1f.x, w1f.y);
        const unsigned long long w2 = pack2(w2f.x, w2f.y);
        const unsigned long long w3 = pack2(w3f.x, w3f.y);

        #pragma unroll
        for (int s = 0; s < 16; s++) {
            const ulonglong2 hd01 = *(const ulonglong2*)(sh_hd + s * HID + j0);
            const ulonglong2 hd23 = *(const ulonglong2*)(sh_hd + s * HID + j0 + 2);
            unsigned long long a0 = acc[s];
            a0 = fma2(hd01.x, w0, a0);
            a0 = fma2(hd01.y, w1, a0);
            a0 = fma2(hd23.x, w2, a0);
            a0 = fma2(hd23.y, w3, a0);
            acc[s] = a0;
        }
    }

    // Epilogue: add s-product for this thread's 2 elements, write bt
    const int idx = tid * 2;            // 0..1022, element index within slab
    const int i  = idx >> 6;
    const int j  = (idx >> 2) & 15;
    const int U0 = idx & 3;             // 0 or 2
    const int l = i >> 2, L = i & 3, r = j >> 2, R = j & 3;
    const float2 bk  = *(const float2*)(b2 + k2);
    const float  eta = 0.001f;

    if (!isTop) {
        #pragma unroll
        for (int s = 0; s < 16; s++) {
            float2 cr; unpack2(acc[s], cr.x, cr.y);
            cr.x += bk.x; cr.y += bk.y;

            const float* sa = sh_s + s * 512;        // s0 slice
            const float* sb = sh_s + s * 512 + 256;  // s1 slice
            const float4 a0 = *(const float4*)(sa + l * 64 + r * 16);
            const float2 b0 = *(const float2*)(sb + L * 64 + R * 16 + 0 * 4 + U0);
            const float2 b1v= *(const float2*)(sb + L * 64 + R * 16 + 1 * 4 + U0);
            const float2 b2v= *(const float2*)(sb + L * 64 + R * 16 + 2 * 4 + U0);
            const float2 b3v= *(const float2*)(sb + L * 64 + R * 16 + 3 * 4 + U0);
            float2 o2;
            o2.x = fmaf(a0.x, b0.x, fmaf(a0.y, b1v.x, fmaf(a0.z, b2v.x, fmaf(a0.w, b3v.x, eta * cr.x))));
            o2.y = fmaf(a0.x, b0.y, fmaf(a0.y, b1v.y, fmaf(a0.z, b2v.y, fmaf(a0.w, b3v.y, eta * cr.y))));
            *(float2*)(g_bt + (n0 + s) * NVEC + k2) = o2;
        }
    } else {
        #pragma unroll
        for (int s = 0; s < 16; s++) {
            float2 cr; unpack2(acc[s], cr.x, cr.y);
            cr.x += bk.x; cr.y += bk.y;

            const float* sa = sh_s + s * 512;        // s2 slice
            const float* sb = sh_s + s * 512 + 256;  // s3 slice
            const float4 c0 = *(const float4*)(sa + l * 64 + r * 16 + U0 * 4);
            const float4 c1 = *(const float4*)(sa + l * 64 + r * 16 + (U0 + 1) * 4);
            const float e0 = sb[L * 64 + R * 16 + 0];
            const float e1 = sb[L * 64 + R * 16 + 4];
            const float e2 = sb[L * 64 + R * 16 + 8];
            const float e3 = sb[L * 64 + R * 16 + 12];
            float2 o2;
            o2.x = fmaf(c0.x, e0, fmaf(c0.y, e1, fmaf(c0.z, e2, fmaf(c0.w, e3, eta * cr.x))));
            o2.y = fmaf(c1.x, e0, fmaf(c1.y, e1, fmaf(c1.z, e2, fmaf(c1.w, e3, eta * cr.y))));
            *(float2*)(g_bt + (n0 + s) * NVEC + k2) = o2;
        }
    }
}

// ---------------------------------------------------------------------------
// Kernel B: scan only. 128 blocks x 512 threads, cp.async double-buffered.
// FFMA2 datapath; v stored duplicated {v,v}; 1 block barrier per x.
// step1: thread (w=j, I=lane&15, ihalf=lane>>4) -> t[I][0..3] via 2 FFMA2/i.
// step2: thread (w=j, J=lane&15, Ihalf) -> v'[w,J] via 2 FFMA2/I.
// ---------------------------------------------------------------------------
__global__ void __launch_bounds__(512) scan_kernel(float* __restrict__ out)
{
    __shared__ float buf[2][2048];                    // [x&1][bot | top]
    __shared__ float sh_t[1024];                      // t[j][I][U], warp-private strips
    __shared__ unsigned long long sh_vd[2][256];      // duplicated v, ping-pong

    const int n   = blockIdx.x;
    const int tid = threadIdx.x;
    const float* src = g_bt + n * NVEC;

    const int half = tid >> 8;
    const int e4   = (tid & 255) * 4;

    cp_async16((uint32_t)__cvta_generic_to_shared(&buf[0][half * 1024 + e4]),
               src + 0 * 1024 + half * 8192 + e4);
    asm volatile("cp.async.commit_group;");
    cp_async16((uint32_t)__cvta_generic_to_shared(&buf[1][half * 1024 + e4]),
               src + 1 * 1024 + half * 8192 + e4);
    asm volatile("cp.async.commit_group;");

    if (tid < 256) {
        const float v = (tid == 0) ? 1.0f : 0.0f;
        sh_vd[0][tid] = pack2(v, v);
    }

    const int w    = tid >> 5;
    const int lane = tid & 31;
    const int I15  = lane & 15;        // I (step1) / J (step2)
    const int ih   = lane >> 4;        // i-half / I-half

    #pragma unroll 1
    for (int x = 0; x < 8; x++) {
        asm volatile("cp.async.wait_group 1;");
        __syncthreads();

        const float* bt = buf[x & 1];
        const float* tp = buf[x & 1] + 1024;
        const unsigned long long* vcur = sh_vd[x & 1];
        unsigned long long*       vnext = sh_vd[(x & 1) ^ 1];

        // step1: t[I,U] = sum_i v[i,I] * bot[i*64 + w*4 + U]
        {
            unsigned long long a01 = 0ull, a23 = 0ull;
            #pragma unroll
            for (int it = 0; it < 8; it++) {
                const int i = ih * 8 + it;
                const ulonglong2 bb = *(const ulonglong2*)(bt + i * 64 + w * 4);
                const unsigned long long vv = vcur[i * 16 + I15];
                a01 = fma2(bb.x, vv, a01);
                a23 = fma2(bb.y, vv, a23);
            }
            float t0, t1, t2, t3;
            unpack2(a01, t0, t1);
            unpack2(a23, t2, t3);
            t0 += __shfl_xor_sync(0xffffffffu, t0, 16);
            t1 += __shfl_xor_sync(0xffffffffu, t1, 16);
            t2 += __shfl_xor_sync(0xffffffffu, t2, 16);
            t3 += __shfl_xor_sync(0xffffffffu, t3, 16);
            if (lane < 16)
                *(float4*)(sh_t + w * 64 + I15 * 4) = make_float4(t0, t1, t2, t3);
        }
        __syncwarp();

        // step2: v'[w,J] = sum_{I,U} t[I,U] * top[I*64 + J*4 + U]
        {
            unsigned long long c01 = 0ull, c23 = 0ull;
            #pragma unroll
            for (int it = 0; it < 8; it++) {
                const int I = ih * 8 + it;
                const ulonglong2 tt = *(const ulonglong2*)(sh_t + w * 64 + I * 4);
                const ulonglong2 pp = *(const ulonglong2*)(tp + I * 64 + I15 * 4);
                c01 = fma2(tt.x, pp.x, c01);
                c23 = fma2(tt.y, pp.y, c23);
            }
            float s0, s1, s2, s3;
            unpack2(c01, s0, s1);
            unpack2(c23, s2, s3);
            float nv = (s0 + s1) + (s2 + s3);
            nv += __shfl_xor_sync(0xffffffffu, nv, 16);
            if (lane < 16) vnext[w * 16 + I15] = pack2(nv, nv);
        }
        __syncthreads();

        if (x < 6) {
            cp_async16((uint32_t)__cvta_generic_to_shared(&buf[x & 1][half * 1024 + e4]),
                       src + (x + 2) * 1024 + half * 8192 + e4);
        }
        asm volatile("cp.async.commit_group;");
    }

    if (tid == 0) {
        float a, b;
        unpack2(sh_vd[0][0], a, b);   // x=7 wrote sh_vd[0]
        out[n] = a;
    }
}

// ---------------------------------------------------------------------------
extern "C" void kernel_launch(void* const* d_in, const int* in_sizes, int n_in,
                              void* d_out, int out_size)
{
    const int*   cfg = (const int*)  d_in[0];
    const float* A   = (const float*)d_in[1];
    const float* W1  = (const float*)d_in[2];
    const float* b1  = (const float*)d_in[3];
    const float* W2  = (const float*)d_in[4];
    const float* b2  = (const float*)d_in[5];
    float* out = (float*)d_out;

    fused_gemm_build<<<dim3(16, 8), 512>>>(cfg, A, W1, b1, W2, b2);
    scan_kernel<<<128, 512>>>(out);
}